// round 16
// baseline (speedup 1.0000x reference)
#include <cuda_runtime.h>

// Problem constants (fixed by setup_inputs)
#define B     128
#define NPIX  2048
#define NBINS 1500
#define NBF   250
#define NREP  256
#define TSIM  1250   // len_bins_sim
#define NBLK  40     // ceil(TSIM/32)
#define N1    ((size_t)B * NREP * NBINS)   // start of gensig region in d_out

#define NCW    14    // copy warps per CTA (warps 0..13)
#define CSEG   8     // segments per copy chunk (5 chunks of 8)
#define NCHK   5
#define RSPLIT 96    // repeats [0,RSPLIT) written by fused kernel
#define RHALF  48    // repeats per fused CTA (RSPLIT/2)
#define RTAIL  (NREP - RSPLIT)   // 160 repeats per batch by tail kernel

// Global staging for the tail writer (published by the fused kernel)
__device__ __align__(16) float g_tl[B * 1500];   // full timeline per batch
__device__ __align__(16) float g_gg[B * 1280];   // gensig per batch (padded)

__device__ __forceinline__ float ftanh(float x) {
    float r; asm("tanh.approx.f32 %0, %1;" : "=f"(r) : "f"(x)); return r;
}

// ---------------------------------------------------------------------------
// FUSED kernel: 256 CTAs x 512 threads, two CTAs per batch (redundant chains,
// zero cross-CTA sync). Writes repeats [0,96) overlapped with the chain, and
// publishes the 1500-float timeline + 1250-float gensig per batch to global
// staging for the tail writer.
//   warp 15   : serial chain via tanh identity, 32 steps/iteration
//   warp 14   : pipelined precompute of next block's history-only partials
//   warps 0-13: copy (init first, then 5 chunks of 8 segments, register-
//               resident spans); warps 0/1 of the half==0 CTA also stage.
// ---------------------------------------------------------------------------
__global__ __launch_bounds__(512, 2) void k_all(
    const float* __restrict__ A,    // (128, 2048)
    const float* __restrict__ st,   // (1500,)
    const float* __restrict__ init, // (128, 250)
    const float* __restrict__ sf,   // (2048,)
    const float* __restrict__ tf,   // (250,)
    const float* __restrict__ fbf,  // (250,)
    const float* __restrict__ bias, // (1,)
    float* __restrict__ out)
{
    __shared__ __align__(16) float sh_tl[1504];   // timeline (init + spikes)
    __shared__ __align__(16) float sh_f[288];     // feedback filter, zero-padded
    __shared__ __align__(16) float sh_fq[288];    // 0.25 * filter (chain taps)
    __shared__ __align__(16) float sh_g[1280];    // drive; overwritten w/ gensig
    __shared__ __align__(16) float sh_tc[256];    // timecourse filter
    __shared__ __align__(16) float sh_st[1504];   // stim_time
    __shared__ float red[512];
    __shared__ float sh_pre[2][32];
    __shared__ int   sh_prog;                     // segments produced (0..NBLK)

    int b    = blockIdx.x >> 1;
    int half = blockIdx.x & 1;
    int tid = threadIdx.x;
    int warp = tid >> 5, lane = tid & 31;
    float* outG = out + N1;

    // ------------------------- setup -------------------------
    if (tid == 0) sh_prog = 0;
    if (tid < NBF) {
        sh_f[tid]  = fbf[tid];
        sh_tc[tid] = tf[tid];
        float iv = init[b * NBF + tid];
        sh_tl[tid] = iv;
        if (half == 0) g_tl[b * 1500 + tid] = iv;   // stage init section
    } else if (tid < 288) sh_f[tid] = 0.f;
    for (int j = tid; j < NBINS; j += 512) sh_st[j] = st[j];
    {   // spatial dot partials: 512 threads x 1 float4 = 2048 floats exactly
        const float4* row4 = (const float4*)(A + (size_t)b * NPIX);
        const float4* sf4  = (const float4*)sf;
        float4 a = row4[tid], f = sf4[tid];
        red[tid] = a.x*f.x + a.y*f.y + a.z*f.z + a.w*f.w;
    }
    __syncthreads();

    if (tid < 288) sh_fq[tid] = 0.25f * sh_f[tid];
    if (warp == 0) {   // reduce spatial dot
        float r = 0.f;
        #pragma unroll
        for (int k = 0; k < 16; k++) r += red[lane + 32 * k];
        #pragma unroll
        for (int o = 16; o > 0; o >>= 1) r += __shfl_xor_sync(0xffffffffu, r, o);
        if (lane == 0) red[0] = r;
    }
    // correlation: 3 t-values per thread (t = tid, tid+512, tid+1024)
    float corr[3];
    #pragma unroll
    for (int u = 0; u < 3; u++) {
        int t = tid + 512 * u;
        float a0 = 0, a1 = 0, a2 = 0, a3 = 0;
        if (t < TSIM) {
            for (int j = 0; j < 248; j += 4) {
                a0 = fmaf(sh_st[t + j],     sh_tc[j],     a0);
                a1 = fmaf(sh_st[t + j + 1], sh_tc[j + 1], a1);
                a2 = fmaf(sh_st[t + j + 2], sh_tc[j + 2], a2);
                a3 = fmaf(sh_st[t + j + 3], sh_tc[j + 3], a3);
            }
            a0 = fmaf(sh_st[t + 248], sh_tc[248], a0);
            a1 = fmaf(sh_st[t + 249], sh_tc[249], a1);
        }
        corr[u] = (a0 + a1) + (a2 + a3);
    }
    __syncthreads();
    {
        float fs = red[0], bv = bias[0];
        #pragma unroll
        for (int u = 0; u < 3; u++) {
            int t = tid + 512 * u;
            if (t < 1280) sh_g[t] = (t < TSIM) ? fmaf(fs, corr[u], bv) : 0.f;
        }
    }
    __syncthreads();

    // ------------------------- role split -------------------------
    if (warp == 15) {
        // ---------------- serial chain (tanh form) ----------------
        {   // block-0 precompute: all taps from initial history
            int lim = 250 - lane;
            float a0 = 0, a1 = 0, a2 = 0, a3 = 0;
            int j = 0;
            for (; j + 4 <= lim; j += 4) {
                a0 = fmaf(sh_tl[lane + j],     sh_f[j],     a0);
                a1 = fmaf(sh_tl[lane + j + 1], sh_f[j + 1], a1);
                a2 = fmaf(sh_tl[lane + j + 2], sh_f[j + 2], a2);
                a3 = fmaf(sh_tl[lane + j + 3], sh_f[j + 3], a3);
            }
            for (; j < lim; j++) a0 = fmaf(sh_tl[lane + j], sh_f[j], a0);
            sh_pre[0][lane] = (a0 + a1) + (a2 + a3);
        }
        int fchain = 250 - lane;   // chain tap base (sh_fq)
        int ffix   = 218 - lane;   // fixup tap base (sh_f)

        // per-lane constant: C = 0.25 * sum_k F_ik  (zeros pad k >= lane)
        float Ci = 0.f;
        #pragma unroll
        for (int k = 0; k < 32; k++) Ci += sh_fq[fchain + k];

        for (int m = 0; m < NBLK; m++) {
            asm volatile("bar.sync 1, 64;" ::: "memory");  // warps 14+15 only
            int T0 = m * 32, t = T0 + lane;
            float part = sh_pre[m & 1][lane] + sh_g[t];

            if (m > 0) {   // fixup: previous block's 32 spikes
                int base = 250 + T0 - 32;
                float a0 = 0, a1 = 0, a2 = 0, a3 = 0;
                #pragma unroll
                for (int k = 0; k < 32; k += 4) {
                    a0 = fmaf(sh_tl[base + k],     sh_f[ffix + k],     a0);
                    a1 = fmaf(sh_tl[base + k + 1], sh_f[ffix + k + 1], a1);
                    a2 = fmaf(sh_tl[base + k + 2], sh_f[ffix + k + 2], a2);
                    a3 = fmaf(sh_tl[base + k + 3], sh_f[ffix + k + 3], a3);
                }
                part += (a0 + a1) + (a2 + a3);
            }

            // Y = gensig/2 with folded halves: Y = 0.5*part + C.
            // Chain: Y += t_k * (0.25*F_ik); taps zero for k >= lane so each
            // lane's Y freezes at its own step; tl = tanh(final Y).
            float Y = fmaf(0.5f, part, Ci);
            float tl = 0.f;
            #pragma unroll
            for (int k = 0; k < 32; k++) {
                tl = ftanh(Y);
                float s = __shfl_sync(0xffffffffu, tl, k);
                Y = fmaf(s, sh_fq[fchain + k], Y);
            }

            int kmax = TSIM - T0; if (kmax > 32) kmax = 32;
            if (lane < kmax) {
                sh_tl[250 + t] = fmaf(0.5f, tl, 0.5f);   // spike = sigmoid(g)
                sh_g[t] = 2.0f * Y;                      // gensig
            }
            __syncwarp();
            if (lane == 0) { __threadfence_block(); *(volatile int*)&sh_prog = m + 1; }
        }
    } else if (warp == 14) {
        // ---------------- pipelined precompute ----------------
        for (int m = 0; m < NBLK; m++) {
            asm volatile("bar.sync 1, 64;" ::: "memory");
            if (m + 1 < NBLK) {   // block m+1 partials over spikes through m-1
                int T0n = m * 32 + 32;
                int lim = 218 - lane;
                float a0 = 0, a1 = 0, a2 = 0, a3 = 0;
                int j = 0;
                for (; j + 4 <= lim; j += 4) {
                    a0 = fmaf(sh_tl[T0n + lane + j],     sh_f[j],     a0);
                    a1 = fmaf(sh_tl[T0n + lane + j + 1], sh_f[j + 1], a1);
                    a2 = fmaf(sh_tl[T0n + lane + j + 2], sh_f[j + 2], a2);
                    a3 = fmaf(sh_tl[T0n + lane + j + 3], sh_f[j + 3], a3);
                }
                for (; j < lim; j++) a0 = fmaf(sh_tl[T0n + lane + j], sh_f[j], a0);
                sh_pre[(m + 1) & 1][lane] = (a0 + a1) + (a2 + a3);
            }
        }
    } else {
        // --- copy warps 0..13: repeats [half*48, half*48+48) + staging ---
        volatile int* prog = &sh_prog;
        const float2* stl2 = (const float2*)sh_tl;
        const float2* sg2  = (const float2*)sh_g;
        int rbase = b * NREP + half * RHALF;
        float2* gtl2 = (float2*)(g_tl + b * 1500);
        float2* ggg2 = (float2*)(g_gg + b * 1280);

        // init section FIRST — no dependency on the chain
        {
            float2 iv[4];
            #pragma unroll
            for (int u = 0; u < 4; u++) {
                int i = lane + 32 * u;
                if (i < 125) iv[u] = stl2[i];
            }
            for (int r = warp; r < RHALF; r += NCW) {
                float2* dT = (float2*)(out + (size_t)(rbase + r) * NBINS);
                #pragma unroll
                for (int u = 0; u < 4; u++) {
                    int i = lane + 32 * u;
                    if (i < 125) dT[i] = iv[u];
                }
            }
        }

        for (int c = 0; c < NCHK; c++) {
            while (*prog < CSEG * (c + 1)) __nanosleep(64);
            // producer's __threadfence_block before the flag store orders the
            // spike/gensig STS ahead of the flag; no consumer fence needed.

            int tlo = 125 + 128 * c;                   // timeline float2 range
            int thi = tlo + 128; if (thi > 750) thi = 750;
            int glo = 128 * c;                         // gensig float2 range
            int ghi = glo + 128; if (ghi > 625) ghi = 625;

            // load spans into registers ONCE per chunk
            float2 tl_r[4], g_r[4];
            #pragma unroll
            for (int u = 0; u < 4; u++) {
                int i = tlo + lane + 32 * u;
                if (i < thi) tl_r[u] = stl2[i];
            }
            #pragma unroll
            for (int u = 0; u < 4; u++) {
                int i = glo + lane + 32 * u;
                if (i < ghi) g_r[u] = sg2[i];
            }

            // stage to global for the tail writer (one CTA per batch)
            if (half == 0) {
                if (warp == 0) {
                    #pragma unroll
                    for (int u = 0; u < 4; u++) {
                        int i = tlo + lane + 32 * u;
                        if (i < thi) gtl2[i] = tl_r[u];
                    }
                } else if (warp == 1) {
                    #pragma unroll
                    for (int u = 0; u < 4; u++) {
                        int i = glo + lane + 32 * u;
                        if (i < ghi) ggg2[i] = g_r[u];
                    }
                }
            }

            // per-row loop: pure stores
            for (int r = warp; r < RHALF; r += NCW) {
                size_t row = (size_t)(rbase + r);
                float2* dT = (float2*)(out + row * NBINS);
                float2* dG = (float2*)(outG + row * TSIM);
                #pragma unroll
                for (int u = 0; u < 4; u++) {
                    int i = tlo + lane + 32 * u;
                    if (i < thi) dT[i] = tl_r[u];
                }
                #pragma unroll
                for (int u = 0; u < 4; u++) {
                    int i = glo + lane + 32 * u;
                    if (i < ghi) dG[i] = g_r[u];
                }
            }
        }
    }
}

// ---------------------------------------------------------------------------
// TAIL writer: R4's proven 3.36 TB/s shape. One short-lived CTA per output
// row; adjacent blocks write adjacent rows; full-row sequential stores
// (float4 timeline, float2 gensig). Reads staging from L2.
// ---------------------------------------------------------------------------
__global__ void k_tail(float* __restrict__ out) {
    int blk = blockIdx.x;
    int b  = blk / RTAIL;
    int rr = blk - b * RTAIL;
    size_t row = (size_t)b * NREP + RSPLIT + rr;
    int tid = threadIdx.x;

    const float4* src = (const float4*)(g_tl + b * 1500);
    float4* dst = (float4*)(out + row * NBINS);
    #pragma unroll
    for (int i = tid; i < 375; i += 256) dst[i] = src[i];

    const float2* sg = (const float2*)(g_gg + b * 1280);
    float2* dg = (float2*)(out + N1 + row * TSIM);
    #pragma unroll
    for (int i = tid; i < 625; i += 256) dg[i] = sg[i];
}

// ---------------------------------------------------------------------------
extern "C" void kernel_launch(void* const* d_in, const int* in_sizes, int n_in,
                              void* d_out, int out_size) {
    const float* A    = (const float*)d_in[0];  // (128, 2048)
    const float* st   = (const float*)d_in[1];  // (1500,)
    const float* init = (const float*)d_in[2];  // (128, 250)
    int off = (n_in >= 8) ? 1 : 0;              // skip n_repeats scalar if present
    const float* sf = (const float*)d_in[3 + off];  // (2048,)
    const float* tf = (const float*)d_in[4 + off];  // (250,)
    const float* fb = (const float*)d_in[5 + off];  // (250,)
    const float* bi = (const float*)d_in[6 + off];  // (1,)

    k_all<<<2 * B, 512>>>(A, st, init, sf, tf, fb, bi, (float*)d_out);
    k_tail<<<B * RTAIL, 256>>>((float*)d_out);
}

// round 17
// speedup vs baseline: 1.0699x; 1.0699x over previous
#include <cuda_runtime.h>

// Problem constants (fixed by setup_inputs)
#define B     128
#define NPIX  2048
#define NBINS 1500
#define NBF   250
#define NREP  256
#define TSIM  1250   // len_bins_sim
#define NB2   20     // 64-step blocks (covers 1280)
#define N1    ((size_t)B * NREP * NBINS)   // start of gensig region in d_out

#define NCW    14    // copy warps per CTA (warps 0..13)
#define NCHK   5     // copy chunks (4 x 64-step segments each)
#define RSPLIT 96    // repeats [0,RSPLIT) written by fused kernel
#define RHALF  48    // repeats per fused CTA
#define RTAIL  (NREP - RSPLIT)   // 160 repeats per batch by tail kernel

// Global staging for the tail writer (published by the fused kernel)
__device__ __align__(16) float g_tl[B * 1500];   // full timeline per batch
__device__ __align__(16) float g_gg[B * 1280];   // gensig per batch (padded)

__device__ __forceinline__ float ftanh(float x) {
    float r; asm("tanh.approx.f32 %0, %1;" : "=f"(r) : "f"(x)); return r;
}

// ---------------------------------------------------------------------------
// FUSED kernel: 256 CTAs x 512 threads, two CTAs per batch (redundant chains,
// zero cross-CTA sync). Writes repeats [0,96) overlapped with the chain and
// publishes timeline/gensig staging for the tail writer.
//
// CHAIN (warp 15): 64-step blocks, TWO time-steps per lane per shfl round.
//   Lane L owns rows a=2L, b=2L+1. Per round r: lane r finalizes
//   tA=tanh(Ya); Yb'=Yb+tA*Fq249 (Fq249 identical for all lanes); tB=tanh(Yb');
//   two shfls broadcast (tA,tB); all lanes apply 4 FMAs with zero-padded taps
//   (rows freeze automatically after their own round; the own-round broadcast
//   commits the tA*Fq249 update so the local temp is consistent).
//   Serial path per round = FMA+TANH+FMA+TANH+SHFL ~ 76cyc for 2 steps,
//   halving the measured ~128cyc/step of the 1-step chain.
// PRECOMPUTE (warp 14): history partials (taps j<=185-i) for the next block.
// Chain does the 64-spike fixup (taps j=186+k-i) for the previous block.
// COPY (warps 0..13): init immediately; 5 chunks of 256 steps, register-
//   resident spans; warps 0/1 of the half==0 CTA also stage to global.
// ---------------------------------------------------------------------------
__global__ __launch_bounds__(512, 2) void k_all(
    const float* __restrict__ A,    // (128, 2048)
    const float* __restrict__ st,   // (1500,)
    const float* __restrict__ init, // (128, 250)
    const float* __restrict__ sf,   // (2048,)
    const float* __restrict__ tf,   // (250,)
    const float* __restrict__ fbf,  // (250,)
    const float* __restrict__ bias, // (1,)
    float* __restrict__ out)
{
    __shared__ __align__(16) float sh_tl[1504];   // timeline (init + spikes)
    __shared__ __align__(16) float sh_f[288];     // feedback filter, zero-padded
    __shared__ __align__(16) float sh_fq[320];    // 0.25*filter, zeros [250,320)
    __shared__ __align__(16) float sh_g[1280];    // drive; overwritten w/ gensig
    __shared__ __align__(16) float sh_tc[256];    // timecourse filter
    __shared__ __align__(16) float sh_st[1504];   // stim_time
    __shared__ float red[512];
    __shared__ float sh_pre[2][64];
    __shared__ int   sh_prog;                     // 64-step segments produced

    int b    = blockIdx.x >> 1;
    int half = blockIdx.x & 1;
    int tid = threadIdx.x;
    int warp = tid >> 5, lane = tid & 31;
    float* outG = out + N1;

    // ------------------------- setup -------------------------
    if (tid == 0) sh_prog = 0;
    if (tid < NBF) {
        sh_f[tid]  = fbf[tid];
        sh_tc[tid] = tf[tid];
        float iv = init[b * NBF + tid];
        sh_tl[tid] = iv;
        if (half == 0) g_tl[b * 1500 + tid] = iv;   // stage init section
    } else if (tid < 288) sh_f[tid] = 0.f;
    for (int j = tid; j < NBINS; j += 512) sh_st[j] = st[j];
    {   // spatial dot partials: 512 threads x 1 float4 = 2048 floats exactly
        const float4* row4 = (const float4*)(A + (size_t)b * NPIX);
        const float4* sf4  = (const float4*)sf;
        float4 a = row4[tid], f = sf4[tid];
        red[tid] = a.x*f.x + a.y*f.y + a.z*f.z + a.w*f.w;
    }
    __syncthreads();

    if (tid < 320) sh_fq[tid] = (tid < NBF) ? 0.25f * sh_f[tid] : 0.f;
    if (warp == 0) {   // reduce spatial dot
        float r = 0.f;
        #pragma unroll
        for (int k = 0; k < 16; k++) r += red[lane + 32 * k];
        #pragma unroll
        for (int o = 16; o > 0; o >>= 1) r += __shfl_xor_sync(0xffffffffu, r, o);
        if (lane == 0) red[0] = r;
    }
    // correlation: 3 t-values per thread (t = tid, tid+512, tid+1024)
    float corr[3];
    #pragma unroll
    for (int u = 0; u < 3; u++) {
        int t = tid + 512 * u;
        float a0 = 0, a1 = 0, a2 = 0, a3 = 0;
        if (t < TSIM) {
            for (int j = 0; j < 248; j += 4) {
                a0 = fmaf(sh_st[t + j],     sh_tc[j],     a0);
                a1 = fmaf(sh_st[t + j + 1], sh_tc[j + 1], a1);
                a2 = fmaf(sh_st[t + j + 2], sh_tc[j + 2], a2);
                a3 = fmaf(sh_st[t + j + 3], sh_tc[j + 3], a3);
            }
            a0 = fmaf(sh_st[t + 248], sh_tc[248], a0);
            a1 = fmaf(sh_st[t + 249], sh_tc[249], a1);
        }
        corr[u] = (a0 + a1) + (a2 + a3);
    }
    __syncthreads();
    {
        float fs = red[0], bv = bias[0];
        #pragma unroll
        for (int u = 0; u < 3; u++) {
            int t = tid + 512 * u;
            if (t < 1280) sh_g[t] = (t < TSIM) ? fmaf(fs, corr[u], bv) : 0.f;
        }
    }
    __syncthreads();

    // ------------------------- role split -------------------------
    if (warp == 15) {
        // ------------- serial chain: 2 steps/lane, 64-step blocks -------------
        int a = 2 * lane;                 // rows a, a+1
        // folded 0.5-constants of in-block spikes (zeros beyond idx 249)
        float Cia = 0.f, Cib = 0.f;
        for (int m2 = 0; m2 < 64; m2++) {
            Cia += sh_fq[250 - a + m2];
            Cib += sh_fq[249 - a + m2];
        }
        float q249 = sh_fq[249];          // L_{b,a}: same constant for all lanes

        {   // block-0 precompute: all taps from initial history
            float p0 = 0.f, p1 = 0.f;
            int la = 250 - a;
            for (int j = 0; j < la; j++) p0 = fmaf(sh_tl[a + j], sh_f[j], p0);
            int lb = 249 - a;
            for (int j = 0; j < lb; j++) p1 = fmaf(sh_tl[a + 1 + j], sh_f[j], p1);
            sh_pre[0][a] = p0; sh_pre[0][a + 1] = p1;
        }

        for (int m = 0; m < NB2; m++) {
            asm volatile("bar.sync 1, 64;" ::: "memory");  // warps 14+15 only
            int T0 = m * 64;
            float Pa = sh_pre[m & 1][a]     + sh_g[T0 + a];
            float Pb = sh_pre[m & 1][a + 1] + sh_g[T0 + a + 1];

            if (m > 0) {   // fixup: previous block's 64 spikes (j = 186+k-i)
                int sb = 250 + T0 - 64;
                float xa0 = 0, xa1 = 0, xb0 = 0, xb1 = 0;
                #pragma unroll
                for (int k = 0; k < 64; k += 2) {
                    float sp0 = sh_tl[sb + k], sp1 = sh_tl[sb + k + 1];
                    xa0 = fmaf(sp0, sh_f[186 + k - a], xa0);
                    xa1 = fmaf(sp1, sh_f[187 + k - a], xa1);
                    xb0 = fmaf(sp0, sh_f[185 + k - a], xb0);
                    xb1 = fmaf(sp1, sh_f[186 + k - a], xb1);
                }
                Pa += (xa0 + xa1);
                Pb += (xb0 + xb1);
            }

            float Ya = fmaf(0.5f, Pa, Cia);
            float Yb = fmaf(0.5f, Pb, Cib);
            float taf = 0.f, tbf = 0.f;   // captured tanh at own round

            #pragma unroll
            for (int r = 0; r < 32; r++) {
                float tA  = ftanh(Ya);
                float tmp = fmaf(tA, q249, Yb);
                float tB  = ftanh(tmp);
                float s0 = __shfl_sync(0xffffffffu, tA, r);
                float s1 = __shfl_sync(0xffffffffu, tB, r);
                if (r == lane) { taf = tA; tbf = tB; }
                // taps for spikes 2r,2r+1 vs rows a,b (zeros freeze the rows)
                float q1 = sh_fq[249 - a + 2 * r];
                float q2 = sh_fq[250 - a + 2 * r];
                float q3 = sh_fq[251 - a + 2 * r];
                Ya = fmaf(s0, q2, fmaf(s1, q3, Ya));
                Yb = fmaf(s0, q1, fmaf(s1, q2, Yb));
            }

            int kmax = TSIM - T0; if (kmax > 64) kmax = 64;
            if (a < kmax) {
                sh_tl[250 + T0 + a] = fmaf(0.5f, taf, 0.5f);   // spike
                sh_g[T0 + a] = 2.0f * Ya;                      // gensig
            }
            if (a + 1 < kmax) {
                sh_tl[251 + T0 + a] = fmaf(0.5f, tbf, 0.5f);
                sh_g[T0 + a + 1] = 2.0f * Yb;
            }
            __syncwarp();
            if (lane == 0) { __threadfence_block(); *(volatile int*)&sh_prog = m + 1; }
        }
    } else if (warp == 14) {
        // ---------------- pipelined precompute (rows a, a+1) ----------------
        int a = 2 * lane;
        for (int m = 0; m < NB2; m++) {
            asm volatile("bar.sync 1, 64;" ::: "memory");
            if (m + 1 < NB2) {   // block m+1 partials: taps j <= 185 - row
                int T0n = m * 64 + 64;
                float p0 = 0, p1 = 0, p2 = 0, p3 = 0;
                int la = 186 - a;
                int j = 0;
                for (; j + 4 <= la; j += 4) {
                    p0 = fmaf(sh_tl[T0n + a + j],     sh_f[j],     p0);
                    p1 = fmaf(sh_tl[T0n + a + j + 1], sh_f[j + 1], p1);
                    p2 = fmaf(sh_tl[T0n + a + j + 2], sh_f[j + 2], p2);
                    p3 = fmaf(sh_tl[T0n + a + j + 3], sh_f[j + 3], p3);
                }
                for (; j < la; j++) p0 = fmaf(sh_tl[T0n + a + j], sh_f[j], p0);
                sh_pre[(m + 1) & 1][a] = (p0 + p1) + (p2 + p3);

                float r0 = 0, r1 = 0, r2 = 0, r3 = 0;
                int lb = 185 - a;
                j = 0;
                for (; j + 4 <= lb; j += 4) {
                    r0 = fmaf(sh_tl[T0n + a + 1 + j],     sh_f[j],     r0);
                    r1 = fmaf(sh_tl[T0n + a + 1 + j + 1], sh_f[j + 1], r1);
                    r2 = fmaf(sh_tl[T0n + a + 1 + j + 2], sh_f[j + 2], r2);
                    r3 = fmaf(sh_tl[T0n + a + 1 + j + 3], sh_f[j + 3], r3);
                }
                for (; j < lb; j++) r0 = fmaf(sh_tl[T0n + a + 1 + j], sh_f[j], r0);
                sh_pre[(m + 1) & 1][a + 1] = (r0 + r1) + (r2 + r3);
            }
        }
    } else {
        // --- copy warps 0..13: repeats [half*48, half*48+48) + staging ---
        volatile int* prog = &sh_prog;
        const float2* stl2 = (const float2*)sh_tl;
        const float2* sg2  = (const float2*)sh_g;
        int rbase = b * NREP + half * RHALF;
        float2* gtl2 = (float2*)(g_tl + b * 1500);
        float2* ggg2 = (float2*)(g_gg + b * 1280);

        // init section FIRST — no dependency on the chain
        {
            float2 iv[4];
            #pragma unroll
            for (int u = 0; u < 4; u++) {
                int i = lane + 32 * u;
                if (i < 125) iv[u] = stl2[i];
            }
            for (int r = warp; r < RHALF; r += NCW) {
                float2* dT = (float2*)(out + (size_t)(rbase + r) * NBINS);
                #pragma unroll
                for (int u = 0; u < 4; u++) {
                    int i = lane + 32 * u;
                    if (i < 125) dT[i] = iv[u];
                }
            }
        }

        for (int c = 0; c < NCHK; c++) {
            while (*prog < 4 * (c + 1)) __nanosleep(64);
            // producer's __threadfence_block before the flag store orders the
            // spike/gensig STS ahead of the flag; no consumer fence needed.

            int tlo = 125 + 128 * c;                   // timeline float2 range
            int thi = tlo + 128; if (thi > 750) thi = 750;
            int glo = 128 * c;                         // gensig float2 range
            int ghi = glo + 128; if (ghi > 625) ghi = 625;

            float2 tl_r[4], g_r[4];
            #pragma unroll
            for (int u = 0; u < 4; u++) {
                int i = tlo + lane + 32 * u;
                if (i < thi) tl_r[u] = stl2[i];
            }
            #pragma unroll
            for (int u = 0; u < 4; u++) {
                int i = glo + lane + 32 * u;
                if (i < ghi) g_r[u] = sg2[i];
            }

            // stage to global for the tail writer (one CTA per batch)
            if (half == 0) {
                if (warp == 0) {
                    #pragma unroll
                    for (int u = 0; u < 4; u++) {
                        int i = tlo + lane + 32 * u;
                        if (i < thi) gtl2[i] = tl_r[u];
                    }
                } else if (warp == 1) {
                    #pragma unroll
                    for (int u = 0; u < 4; u++) {
                        int i = glo + lane + 32 * u;
                        if (i < ghi) ggg2[i] = g_r[u];
                    }
                }
            }

            for (int r = warp; r < RHALF; r += NCW) {
                size_t row = (size_t)(rbase + r);
                float2* dT = (float2*)(out + row * NBINS);
                float2* dG = (float2*)(outG + row * TSIM);
                #pragma unroll
                for (int u = 0; u < 4; u++) {
                    int i = tlo + lane + 32 * u;
                    if (i < thi) dT[i] = tl_r[u];
                }
                #pragma unroll
                for (int u = 0; u < 4; u++) {
                    int i = glo + lane + 32 * u;
                    if (i < ghi) dG[i] = g_r[u];
                }
            }
        }
    }
}

// ---------------------------------------------------------------------------
// TAIL writer: proven ~4 TB/s shape. One short-lived CTA per output row;
// adjacent blocks -> adjacent rows; full-row sequential stores.
// ---------------------------------------------------------------------------
__global__ void k_tail(float* __restrict__ out) {
    int blk = blockIdx.x;
    int b  = blk / RTAIL;
    int rr = blk - b * RTAIL;
    size_t row = (size_t)b * NREP + RSPLIT + rr;
    int tid = threadIdx.x;

    const float4* src = (const float4*)(g_tl + b * 1500);
    float4* dst = (float4*)(out + row * NBINS);
    #pragma unroll
    for (int i = tid; i < 375; i += 256) dst[i] = src[i];

    const float2* sg = (const float2*)(g_gg + b * 1280);
    float2* dg = (float2*)(out + N1 + row * TSIM);
    #pragma unroll
    for (int i = tid; i < 625; i += 256) dg[i] = sg[i];
}

// ---------------------------------------------------------------------------
extern "C" void kernel_launch(void* const* d_in, const int* in_sizes, int n_in,
                              void* d_out, int out_size) {
    const float* A    = (const float*)d_in[0];  // (128, 2048)
    const float* st   = (const float*)d_in[1];  // (1500,)
    const float* init = (const float*)d_in[2];  // (128, 250)
    int off = (n_in >= 8) ? 1 : 0;              // skip n_repeats scalar if present
    const float* sf = (const float*)d_in[3 + off];  // (2048,)
    const float* tf = (const float*)d_in[4 + off];  // (250,)
    const float* fb = (const float*)d_in[5 + off];  // (250,)
    const float* bi = (const float*)d_in[6 + off];  // (1,)

    k_all<<<2 * B, 512>>>(A, st, init, sf, tf, fb, bi, (float*)d_out);
    k_tail<<<B * RTAIL, 256>>>((float*)d_out);
}